// round 9
// baseline (speedup 1.0000x reference)
#include <cuda_runtime.h>
#include <cstdint>

#define B_   256
#define D_   784
#define H_   1024
#define T_   10
#define NCH  18
#define CHLEN 44

#define KNEG (-1.4426950408889634f)   // -log2(e)

typedef unsigned long long ull;

// ---------------- scratch ----------------
__device__ __align__(16) float g_Wt[D_ * H_];            // (-log2e)*W transposed: [D][H]
__device__ __align__(16) float g_Apre[NCH * B_ * H_];    // scaled chunk-start accumulators
__device__ __align__(16) float g_part[D_ * 8 * 2 * 320]; // partial logits [d][tile][hh][t][L]

// ---------------- helpers ----------------
__device__ __forceinline__ float ex2f(float x) {
    float y; asm("ex2.approx.f32 %0, %1;" : "=f"(y) : "f"(x)); return y;
}
__device__ __forceinline__ float rcpf(float x) {
    float y; asm("rcp.approx.f32 %0, %1;" : "=f"(y) : "f"(x)); return y;
}
__device__ __forceinline__ ull fma2_(ull a, ull b, ull c) {
    ull d; asm("fma.rn.f32x2 %0, %1, %2, %3;" : "=l"(d) : "l"(a), "l"(b), "l"(c)); return d;
}
__device__ __forceinline__ ull pack2_(float lo, float hi) {
    ull d; asm("mov.b64 %0, {%1, %2};" : "=l"(d) : "f"(lo), "f"(hi)); return d;
}
__device__ __forceinline__ void unpack2_(ull v, float& lo, float& hi) {
    asm("mov.b64 {%0, %1}, %2;" : "=f"(lo), "=f"(hi) : "l"(v));
}
__device__ __forceinline__ void cp_async16(float* s, const float* g) {
    unsigned sa = (unsigned)__cvta_generic_to_shared(s);
    asm volatile("cp.async.ca.shared.global [%0], [%1], 16;\n" :: "r"(sa), "l"(g));
}
__device__ __forceinline__ void cp_commit() {
    asm volatile("cp.async.commit_group;\n" ::: "memory");
}

// ---------------- K1: transpose W [H][D] -> (-log2e)*Wt [D][H] ----------------
__global__ void k_transW(const float* __restrict__ W) {
    __shared__ float tile[32][33];
    int d = blockIdx.x * 32 + threadIdx.x;
    int h = blockIdx.y * 32 + threadIdx.y;
#pragma unroll
    for (int j = 0; j < 32; j += 8)
        if (d < D_) tile[threadIdx.y + j][threadIdx.x] = W[(h + j) * D_ + d] * KNEG;
    __syncthreads();
    int ho = blockIdx.y * 32 + threadIdx.x;
    int do_ = blockIdx.x * 32 + threadIdx.y;
#pragma unroll
    for (int j = 0; j < 32; j += 8)
        if (do_ + j < D_) g_Wt[(do_ + j) * H_ + ho] = tile[threadIdx.x][threadIdx.y + j];
}

// ---------------- K2: chunk sums (grid 32x18x2, 8 acc/thread) ----------------
__global__ __launch_bounds__(512) void k_chunksum(const int* __restrict__ x) {
    int bg = blockIdx.x;        // 0..31 (8 batches each)
    int k  = blockIdx.y;        // 0..NCH-1
    int i0 = k * CHLEN;
    int len = min(CHLEN, D_ - i0);
    __shared__ float xs2[CHLEN * 8];
    int tid = threadIdx.x;
    for (int idx = tid; idx < len * 8; idx += 512) {
        int j = idx >> 3, b = idx & 7;
        xs2[idx] = (float)x[(size_t)(bg * 8 + b) * D_ + i0 + j];
    }
    __syncthreads();
    int h0 = blockIdx.z * 512 + tid;
    float acc[8];
#pragma unroll
    for (int b = 0; b < 8; b++) acc[b] = 0.f;
    float wn1 = g_Wt[i0 * H_ + h0];
    float wn2 = (len > 1) ? g_Wt[(i0 + 1) * H_ + h0] : 0.f;
    for (int j = 0; j < len; j++) {
        float wv = wn1;
        wn1 = wn2;
        if (j + 2 < len) wn2 = g_Wt[(i0 + j + 2) * H_ + h0];
        const float* xr = &xs2[j * 8];
#pragma unroll
        for (int b = 0; b < 8; b++)
            acc[b] = fmaf(xr[b], wv, acc[b]);
    }
#pragma unroll
    for (int b = 0; b < 8; b++)
        g_Apre[(size_t)(k * B_ + bg * 8 + b) * H_ + h0] = acc[b];
}

// ---------------- K3: exclusive prefix, MLP=18 ----------------
__global__ void k_prefix(const float* __restrict__ c) {
    int idx = blockIdx.x * 256 + threadIdx.x;   // 0..131071
    int b  = idx >> 9;
    int h0 = (idx & 511) * 2;
    float2 v[NCH];
#pragma unroll
    for (int k = 0; k < NCH; k++)
        v[k] = *(const float2*)&g_Apre[(size_t)(k * B_ + b) * H_ + h0];
    float2 acc = *(const float2*)&c[h0];
    acc.x *= KNEG; acc.y *= KNEG;
#pragma unroll
    for (int k = 0; k < NCH; k++) {
        *(float2*)&g_Apre[(size_t)(k * B_ + b) * H_ + h0] = acc;
        acc.x += v[k].x; acc.y += v[k].y;
    }
}

// ---------------- K4: main kernel (half-H blocks, 2 blocks/SM) ----------------
// smem (floats): V 3*5120, W 3*512, RED 2*2560
#define SM_V   0
#define SM_W   (3 * 5120)
#define SM_RED (SM_W + 3 * 512)
#define SM_FLOATS (SM_RED + 2 * 2560)   // 22016 floats = 88064 B

__device__ __forceinline__ void stage(float* sm, int i, int srel, int hbase, int tid,
                                      const float* __restrict__ V) {
    const int bb = srel % 3;
    const float* vg = V + (size_t)i * (T_ * H_) + (size_t)hbase * T_;
    float* vs = sm + SM_V + bb * 5120;
#pragma unroll
    for (int q = 0; q < 5; q++)
        cp_async16(vs + (tid + q * 256) * 4, vg + (tid + q * 256) * 4);
    if (tid < 128)
        cp_async16(sm + SM_W + bb * 512 + tid * 4, g_Wt + (size_t)i * H_ + hbase + tid * 4);
}

__device__ __forceinline__ void step_compute(float* sm, ull* a2, float xvf,
                                             int hl, int w, int L, int srel) {
    const float* Vp = sm + SM_V + (srel % 3) * 5120;
    const float* Wp = sm + SM_W + (srel % 3) * 512;
    const ull x2 = pack2_(xvf, xvf);

    ull acc[5];
#pragma unroll
    for (int j = 0; j < 5; j++) acc[j] = 0ull;

    float se, so;
    {
        float f0, f1;
        unpack2_(a2[0], f0, f1);
        se = rcpf(1.f + ex2f(f0));
        so = rcpf(1.f + ex2f(f1));
    }

    ulonglong2 wv;
#pragma unroll
    for (int u = 0; u < 32; u++) {          // h-pair (hl+2u, hl+2u+1); hl even
        float ne = 0.f, no = 0.f;
        if (u < 31) {
            float f0, f1;
            unpack2_(a2[u + 1], f0, f1);
            ne = rcpf(1.f + ex2f(f0));
            no = rcpf(1.f + ex2f(f1));
        }
        if ((u & 1) == 0) wv = *(const ulonglong2*)(Wp + hl + 2 * u);
        a2[u] = fma2_(x2, (u & 1) ? wv.y : wv.x, a2[u]);

        const float* vre = Vp + (hl + 2 * u) * T_;   // even row: 16B aligned
        const ull sse = pack2_(se, se);
        const ull sso = pack2_(so, so);
        const ulonglong2 e01 = *(const ulonglong2*)(vre);
        const ulonglong2 e23 = *(const ulonglong2*)(vre + 4);
        const ull        e4  = *(const ull*)       (vre + 8);
        acc[0] = fma2_(sse, e01.x, acc[0]);
        acc[1] = fma2_(sse, e01.y, acc[1]);
        acc[2] = fma2_(sse, e23.x, acc[2]);
        acc[3] = fma2_(sse, e23.y, acc[3]);
        acc[4] = fma2_(sse, e4,   acc[4]);
        const ull        o0  = *(const ull*)       (vre + 10);
        const ulonglong2 o12 = *(const ulonglong2*)(vre + 12);
        const ulonglong2 o34 = *(const ulonglong2*)(vre + 16);
        acc[0] = fma2_(sso, o0,    acc[0]);
        acc[1] = fma2_(sso, o12.x, acc[1]);
        acc[2] = fma2_(sso, o12.y, acc[2]);
        acc[3] = fma2_(sso, o34.x, acc[3]);
        acc[4] = fma2_(sso, o34.y, acc[4]);

        se = ne; so = no;
    }

    float* red = sm + SM_RED + (srel & 1) * 2560;
#pragma unroll
    for (int j = 0; j < 5; j++) {
        float lo, hi;
        unpack2_(acc[j], lo, hi);
        red[(w * T_ + 2 * j)     * 32 + L] = lo;
        red[(w * T_ + 2 * j + 1) * 32 + L] = hi;
    }
}

__device__ __forceinline__ void reduce_store(const float* sm, float* gp_base,
                                             int sdone, int L) {
    const float* red = sm + SM_RED + (sdone & 1) * 2560;
    float l[T_];
#pragma unroll
    for (int t = 0; t < T_; t++) l[t] = 0.f;
#pragma unroll
    for (int ww = 0; ww < 8; ww++)
#pragma unroll
        for (int t = 0; t < T_; t++)
            l[t] += red[(ww * T_ + t) * 32 + L];
    float* gp = gp_base + (size_t)sdone * (8 * 2 * 320);
#pragma unroll
    for (int t = 0; t < T_; t++)
        gp[t * 32 + L] = l[t];
}

__global__ __launch_bounds__(256, 2) void k_main(const int* __restrict__ xi,
                                                 const float* __restrict__ V) {
    extern __shared__ float sm[];
    const int tid   = threadIdx.x;
    const int w     = tid >> 5;       // 0..7
    const int L     = tid & 31;       // lane = batch within tile
    const int tile  = blockIdx.x;     // 0..7
    const int chunk = blockIdx.y;     // 0..NCH-1
    const int hh    = blockIdx.z;     // 0..1
    const int i0  = chunk * CHLEN;
    const int len = min(CHLEN, D_ - i0);
    const int hbase = hh * 512;
    const int hl  = w * 64;           // local h within half
    const int h0  = hbase + hl;       // global h

    // a (scaled) in registers: 64 h as 32 f32x2 pairs
    ull a2[32];
    {
        const ulonglong2* ag = (const ulonglong2*)(g_Apre +
            (size_t)(chunk * B_ + tile * 32 + L) * H_ + h0);
#pragma unroll
        for (int g = 0; g < 16; g++) {
            ulonglong2 v = ag[g];
            a2[2 * g]     = v.x;
            a2[2 * g + 1] = v.y;
        }
    }

    stage(sm, i0, 0, hbase, tid, V); cp_commit();
    if (len > 1) { stage(sm, i0 + 1, 1, hbase, tid, V); cp_commit(); }

    const int* xrow = xi + (size_t)(tile * 32 + L) * D_ + i0;
    float xn1 = (float)__ldg(xrow + 0);
    float xn2 = (float)__ldg(xrow + 1);

    // partial-logit base for this (tile, hh): g_part[d][tile][hh][t][L]
    float* gp_base = g_part + ((size_t)i0 * 8 + tile) * (2 * 320) + hh * 320;

    for (int s = 0; s < len; s++) {
        if (s + 1 < len) asm volatile("cp.async.wait_group 1;\n" ::: "memory");
        else             asm volatile("cp.async.wait_group 0;\n" ::: "memory");
        __syncthreads();

        const float xc = xn1;
        xn1 = xn2;
        if (s + 2 < len) {
            xn2 = (float)__ldg(xrow + s + 2);
            stage(sm, i0 + s + 2, s + 2, hbase, tid, V); cp_commit();
        }

        if (s >= 1 && w == ((s - 1) & 7))
            reduce_store(sm, gp_base, s - 1, L);

        step_compute(sm, a2, xc, hl, w, L, s);
    }

    __syncthreads();
    if (w == ((len - 1) & 7))
        reduce_store(sm, gp_base, len - 1, L);
}

// ---------------- K5: combine halves + bias + softmax ----------------
__global__ __launch_bounds__(320) void k_softmax(const float* __restrict__ bias,
                                                 float* __restrict__ out) {
    __shared__ float lg[320];
    const int d    = blockIdx.x;      // 0..783
    const int tile = blockIdx.y;      // 0..7
    const int tid  = threadIdx.x;     // 0..319
    const int t = tid >> 5;
    const int L = tid & 31;
    const float* gp = g_part + ((size_t)d * 8 + tile) * (2 * 320);
    lg[t * 32 + L] = gp[t * 32 + L] + gp[320 + t * 32 + L] + bias[d * T_ + t];
    __syncthreads();
    if (tid < 32) {
        float l[T_];
#pragma unroll
        for (int q = 0; q < T_; q++) l[q] = lg[q * 32 + tid];
        float mx = l[0];
#pragma unroll
        for (int q = 1; q < T_; q++) mx = fmaxf(mx, l[q]);
        float e[T_]; float sum = 0.f;
#pragma unroll
        for (int q = 0; q < T_; q++) {
            e[q] = ex2f((l[q] - mx) * 1.4426950408889634f);
            sum += e[q];
        }
        const float r = rcpf(sum);
        float* op = out + (size_t)(tile * 32 + tid) * (T_ * D_) + d;
#pragma unroll
        for (int q = 0; q < T_; q++) op[q * D_] = e[q] * r;
    }
}

// ---------------- launch ----------------
extern "C" void kernel_launch(void* const* d_in, const int* in_sizes, int n_in,
                              void* d_out, int out_size) {
    const int*   x    = (const int*)d_in[0];
    const float* W    = (const float*)d_in[1];
    const float* c    = (const float*)d_in[2];
    const float* V    = (const float*)d_in[3];
    const float* bias = (const float*)d_in[4];
    float* out = (float*)d_out;

    static_assert(2 * SM_FLOATS * 4 <= 232448, "smem budget for 2 blocks/SM");
    cudaFuncSetAttribute(k_main, cudaFuncAttributeMaxDynamicSharedMemorySize,
                         SM_FLOATS * (int)sizeof(float));

    k_transW<<<dim3((D_ + 31) / 32, H_ / 32), dim3(32, 8)>>>(W);     // launch 1
    k_chunksum<<<dim3(32, NCH, 2), 512>>>(x);                        // launch 2
    k_prefix<<<(B_ * H_ / 2) / 256, 256>>>(c);                       // launch 3
    k_main<<<dim3(8, NCH, 2), 256, SM_FLOATS * (int)sizeof(float)>>>(x, V);  // launch 4 -> profiled
    k_softmax<<<dim3(D_, 8), 320>>>(bias, out);                      // launch 5
}

// round 10
// speedup vs baseline: 1.0441x; 1.0441x over previous
#include <cuda_runtime.h>
#include <cstdint>

#define B_   256
#define D_   784
#define H_   1024
#define T_   10
#define NCH  18
#define CHLEN 44

#define KNEG (-1.4426950408889634f)   // -log2(e)

typedef unsigned long long ull;

// ---------------- scratch ----------------
__device__ __align__(16) float g_Wt[D_ * H_];            // (-log2e)*W transposed: [D][H]
__device__ __align__(16) float g_Apre[NCH * B_ * H_];    // scaled chunk-start accumulators
__device__ __align__(16) ull   g_part[D_ * 4 * 4 * 320]; // partial logits [d][tile4][q4][5j][64c]

// ---------------- helpers ----------------
__device__ __forceinline__ float ex2f(float x) {
    float y; asm("ex2.approx.f32 %0, %1;" : "=f"(y) : "f"(x)); return y;
}
__device__ __forceinline__ float rcpf(float x) {
    float y; asm("rcp.approx.f32 %0, %1;" : "=f"(y) : "f"(x)); return y;
}
__device__ __forceinline__ ull fma2_(ull a, ull b, ull c) {
    ull d; asm("fma.rn.f32x2 %0, %1, %2, %3;" : "=l"(d) : "l"(a), "l"(b), "l"(c)); return d;
}
__device__ __forceinline__ ull add2_(ull a, ull b) {
    ull d; asm("add.rn.f32x2 %0, %1, %2;" : "=l"(d) : "l"(a), "l"(b)); return d;
}
__device__ __forceinline__ ull pack2_(float lo, float hi) {
    ull d; asm("mov.b64 %0, {%1, %2};" : "=l"(d) : "f"(lo), "f"(hi)); return d;
}
__device__ __forceinline__ void unpack2_(ull v, float& lo, float& hi) {
    asm("mov.b64 {%0, %1}, %2;" : "=f"(lo), "=f"(hi) : "l"(v));
}
__device__ __forceinline__ void cp_async16(float* s, const float* g) {
    unsigned sa = (unsigned)__cvta_generic_to_shared(s);
    asm volatile("cp.async.ca.shared.global [%0], [%1], 16;\n" :: "r"(sa), "l"(g));
}
__device__ __forceinline__ void cp_commit() {
    asm volatile("cp.async.commit_group;\n" ::: "memory");
}

// ---------------- K1: transpose W [H][D] -> (-log2e)*Wt [D][H] ----------------
__global__ void k_transW(const float* __restrict__ W) {
    __shared__ float tile[32][33];
    int d = blockIdx.x * 32 + threadIdx.x;
    int h = blockIdx.y * 32 + threadIdx.y;
#pragma unroll
    for (int j = 0; j < 32; j += 8)
        if (d < D_) tile[threadIdx.y + j][threadIdx.x] = W[(h + j) * D_ + d] * KNEG;
    __syncthreads();
    int ho = blockIdx.y * 32 + threadIdx.x;
    int do_ = blockIdx.x * 32 + threadIdx.y;
#pragma unroll
    for (int j = 0; j < 32; j += 8)
        if (do_ + j < D_) g_Wt[(do_ + j) * H_ + ho] = tile[threadIdx.x][threadIdx.y + j];
}

// ---------------- K2: chunk sums ----------------
__global__ __launch_bounds__(512) void k_chunksum(const int* __restrict__ x) {
    int bg = blockIdx.x;        // 0..31 (8 batches each)
    int k  = blockIdx.y;
    int i0 = k * CHLEN;
    int len = min(CHLEN, D_ - i0);
    __shared__ float xs2[CHLEN * 8];
    int tid = threadIdx.x;
    for (int idx = tid; idx < len * 8; idx += 512) {
        int j = idx >> 3, b = idx & 7;
        xs2[idx] = (float)x[(size_t)(bg * 8 + b) * D_ + i0 + j];
    }
    __syncthreads();
    int h0 = blockIdx.z * 512 + tid;
    float acc[8];
#pragma unroll
    for (int b = 0; b < 8; b++) acc[b] = 0.f;
    float wn1 = g_Wt[i0 * H_ + h0];
    float wn2 = (len > 1) ? g_Wt[(i0 + 1) * H_ + h0] : 0.f;
    for (int j = 0; j < len; j++) {
        float wv = wn1;
        wn1 = wn2;
        if (j + 2 < len) wn2 = g_Wt[(i0 + j + 2) * H_ + h0];
        const float* xr = &xs2[j * 8];
#pragma unroll
        for (int b = 0; b < 8; b++)
            acc[b] = fmaf(xr[b], wv, acc[b]);
    }
#pragma unroll
    for (int b = 0; b < 8; b++)
        g_Apre[(size_t)(k * B_ + bg * 8 + b) * H_ + h0] = acc[b];
}

// ---------------- K3: exclusive prefix, MLP=18 ----------------
__global__ void k_prefix(const float* __restrict__ c) {
    int idx = blockIdx.x * 256 + threadIdx.x;
    int b  = idx >> 9;
    int h0 = (idx & 511) * 2;
    float2 v[NCH];
#pragma unroll
    for (int k = 0; k < NCH; k++)
        v[k] = *(const float2*)&g_Apre[(size_t)(k * B_ + b) * H_ + h0];
    float2 acc = *(const float2*)&c[h0];
    acc.x *= KNEG; acc.y *= KNEG;
#pragma unroll
    for (int k = 0; k < NCH; k++) {
        *(float2*)&g_Apre[(size_t)(k * B_ + b) * H_ + h0] = acc;
        acc.x += v[k].x; acc.y += v[k].y;
    }
}

// ---------------- K4: main kernel (64 batches x 256 h per block) ----------------
// smem (floats):
#define SM_V   0                        // 3 * 2560 = 7680
#define SM_W   7680                     // 3 * 256  =  768
#define SM_RED 8448                     // 2 * 5120 = 10240 (as ull pairs)
#define SM_FLOATS 18688                 // 74752 B; x2 blocks = 149504 B

__device__ __forceinline__ void stage(float* sm, int i, int srel, int hbase, int tid,
                                      const float* __restrict__ V) {
    const int bb = srel % 3;
    const float* vg = V + (size_t)i * (T_ * H_) + (size_t)hbase * T_;   // 2560 floats
    float* vs = sm + SM_V + bb * 2560;
    cp_async16(vs + tid * 4, vg + tid * 4);
    if (tid < 128) cp_async16(vs + (tid + 512) * 4, vg + (tid + 512) * 4);
    else if (tid < 192)
        cp_async16(sm + SM_W + bb * 256 + (tid - 128) * 4,
                   g_Wt + (size_t)i * H_ + hbase + (tid - 128) * 4);
    cp_async16(vs + (tid + 256) * 4, vg + (tid + 256) * 4);
}

__device__ __forceinline__ void step_compute(float* sm, ull* a2, ull x2,
                                             int hl, int w, int L, int srel) {
    const float* Vp = sm + SM_V + (srel % 3) * 2560;
    const float* Wp = sm + SM_W + (srel % 3) * 256;

    ull accA[5], accB[5];
#pragma unroll
    for (int j = 0; j < 5; j++) { accA[j] = 0ull; accB[j] = 0ull; }

    float sb0, sb1;
    {
        float f0, f1;
        unpack2_(a2[0], f0, f1);
        sb0 = rcpf(1.f + ex2f(f0));
        sb1 = rcpf(1.f + ex2f(f1));
    }

#pragma unroll
    for (int u = 0; u < 32; u++) {      // h = hbase + hl + u; a2[u] = (a_b0, a_b1)
        float nb0 = 0.f, nb1 = 0.f;
        if (u < 31) {
            float f0, f1;
            unpack2_(a2[u + 1], f0, f1);
            nb0 = rcpf(1.f + ex2f(f0));
            nb1 = rcpf(1.f + ex2f(f1));
        }
        const float wv = Wp[hl + u];
        a2[u] = fma2_(x2, pack2_(wv, wv), a2[u]);

        const float* vr = Vp + (hl + u) * T_;     // 40B rows, 8B aligned
        const ull s0 = pack2_(sb0, sb0);
        const ull s1 = pack2_(sb1, sb1);
#pragma unroll
        for (int j = 0; j < 5; j++) {
            const ull vv = *(const ull*)(vr + 2 * j);
            accA[j] = fma2_(s0, vv, accA[j]);
            accB[j] = fma2_(s1, vv, accB[j]);
        }
        sb0 = nb0; sb1 = nb1;
    }

    float* red = sm + SM_RED + (srel & 1) * 5120;
#pragma unroll
    for (int j = 0; j < 5; j++) {
        *(ull*)(red + ((w * 5 + j) * 64 + L) * 2)      = accA[j];
        *(ull*)(red + ((w * 5 + j) * 64 + 32 + L) * 2) = accB[j];
    }
}

__device__ __forceinline__ void reduce_store(const float* sm, ull* gp, int sdone, int L) {
    const float* red = sm + SM_RED + (sdone & 1) * 5120;
#pragma unroll
    for (int j = 0; j < 5; j++)
#pragma unroll
        for (int p = 0; p < 2; p++) {
            const int col = p * 32 + L;
            ull s = *(const ull*)(red + ((0 * 5 + j) * 64 + col) * 2);
#pragma unroll
            for (int ww = 1; ww < 8; ww++)
                s = add2_(s, *(const ull*)(red + ((ww * 5 + j) * 64 + col) * 2));
            gp[j * 64 + col] = s;
        }
}

__global__ __launch_bounds__(256, 2) void k_main(const int* __restrict__ xi,
                                                 const float* __restrict__ V) {
    extern __shared__ float sm[];
    const int tid   = threadIdx.x;
    const int w     = tid >> 5;       // 0..7
    const int L     = tid & 31;
    const int tile  = blockIdx.x;     // 0..3  (64 batches)
    const int chunk = blockIdx.y;     // 0..NCH-1
    const int qh    = blockIdx.z;     // 0..3  (256 h)
    const int i0  = chunk * CHLEN;
    const int len = min(CHLEN, D_ - i0);
    const int hbase = qh * 256;
    const int hl  = w * 32;           // local h within quarter
    const int h0  = hbase + hl;

    // a2[u] = (A[b0][h0+u], A[b1][h0+u]); b0 = tile*64+L, b1 = b0+32
    ull a2[32];
    {
        const float* ap0 = g_Apre + ((size_t)(chunk * B_ + tile * 64 + L)) * H_ + h0;
        const float* ap1 = ap0 + (size_t)32 * H_;
#pragma unroll
        for (int g = 0; g < 8; g++) {
            float4 va = *(const float4*)(ap0 + 4 * g);
            float4 vb = *(const float4*)(ap1 + 4 * g);
            a2[4 * g + 0] = pack2_(va.x, vb.x);
            a2[4 * g + 1] = pack2_(va.y, vb.y);
            a2[4 * g + 2] = pack2_(va.z, vb.z);
            a2[4 * g + 3] = pack2_(va.w, vb.w);
        }
    }

    stage(sm, i0, 0, hbase, tid, V); cp_commit();
    if (len > 1) { stage(sm, i0 + 1, 1, hbase, tid, V); cp_commit(); }

    const int* xrow0 = xi + (size_t)(tile * 64 + L) * D_ + i0;
    const int* xrow1 = xrow0 + (size_t)32 * D_;
    float x0buf[2], x1buf[2];
    x0buf[0] = (float)__ldg(xrow0);     x1buf[0] = (float)__ldg(xrow1);
    x0buf[1] = (len > 1) ? (float)__ldg(xrow0 + 1) : 0.f;
    x1buf[1] = (len > 1) ? (float)__ldg(xrow1 + 1) : 0.f;

    for (int s = 0; s < len; s++) {
        if (s + 1 < len) asm volatile("cp.async.wait_group 1;\n" ::: "memory");
        else             asm volatile("cp.async.wait_group 0;\n" ::: "memory");
        __syncthreads();

        const ull x2 = pack2_(x0buf[s & 1], x1buf[s & 1]);
        if (s + 2 < len) {
            x0buf[s & 1] = (float)__ldg(xrow0 + s + 2);
            x1buf[s & 1] = (float)__ldg(xrow1 + s + 2);
            stage(sm, i0 + s + 2, s + 2, hbase, tid, V); cp_commit();
        }

        if (s >= 1 && w == ((s - 1) & 7)) {
            ull* gp = g_part + ((size_t)((i0 + s - 1) * 4 + tile) * 4 + qh) * 320;
            reduce_store(sm, gp, s - 1, L);
        }

        step_compute(sm, a2, x2, hl, w, L, s);
    }

    __syncthreads();
    if (w == ((len - 1) & 7)) {
        ull* gp = g_part + ((size_t)((i0 + len - 1) * 4 + tile) * 4 + qh) * 320;
        reduce_store(sm, gp, len - 1, L);
    }
}

// ---------------- K5: combine quarters + bias + softmax ----------------
__global__ __launch_bounds__(320) void k_softmax(const float* __restrict__ bias,
                                                 float* __restrict__ out) {
    __shared__ float lg[T_ * 66];
    const int d    = blockIdx.x;      // 0..783
    const int tile = blockIdx.y;      // 0..3
    const int tid  = threadIdx.x;     // 0..319: (j, c)
    const int j = tid >> 6;
    const int c = tid & 63;
    const ull* gp = g_part + ((size_t)(d * 4 + tile) * 4) * 320;
    ull v = gp[tid];
    v = add2_(v, gp[320 + tid]);
    v = add2_(v, gp[640 + tid]);
    v = add2_(v, gp[960 + tid]);
    float lo, hi;
    unpack2_(v, lo, hi);
    lg[(2 * j)     * 66 + c] = lo + bias[d * T_ + 2 * j];
    lg[(2 * j + 1) * 66 + c] = hi + bias[d * T_ + 2 * j + 1];
    __syncthreads();
    if (tid < 64) {
        float l[T_];
#pragma unroll
        for (int t = 0; t < T_; t++) l[t] = lg[t * 66 + tid];
        float mx = l[0];
#pragma unroll
        for (int t = 1; t < T_; t++) mx = fmaxf(mx, l[t]);
        float e[T_]; float sum = 0.f;
#pragma unroll
        for (int t = 0; t < T_; t++) {
            e[t] = ex2f((l[t] - mx) * 1.4426950408889634f);
            sum += e[t];
        }
        const float r = rcpf(sum);
        float* op = out + (size_t)(tile * 64 + tid) * (T_ * D_) + d;
#pragma unroll
        for (int t = 0; t < T_; t++) op[t * D_] = e[t] * r;
    }
}

// ---------------- launch ----------------
extern "C" void kernel_launch(void* const* d_in, const int* in_sizes, int n_in,
                              void* d_out, int out_size) {
    const int*   x    = (const int*)d_in[0];
    const float* W    = (const float*)d_in[1];
    const float* c    = (const float*)d_in[2];
    const float* V    = (const float*)d_in[3];
    const float* bias = (const float*)d_in[4];
    float* out = (float*)d_out;

    static_assert(2 * SM_FLOATS * 4 <= 232448, "smem budget for 2 blocks/SM");
    cudaFuncSetAttribute(k_main, cudaFuncAttributeMaxDynamicSharedMemorySize,
                         SM_FLOATS * (int)sizeof(float));

    k_transW<<<dim3((D_ + 31) / 32, H_ / 32), dim3(32, 8)>>>(W);     // launch 1
    k_chunksum<<<dim3(32, NCH, 2), 512>>>(x);                        // launch 2
    k_prefix<<<(B_ * H_ / 2) / 256, 256>>>(c);                       // launch 3
    k_main<<<dim3(4, NCH, 4), 256, SM_FLOATS * (int)sizeof(float)>>>(x, V);  // launch 4 -> profiled
    k_softmax<<<dim3(D_, 4), 320>>>(bias, out);                      // launch 5
}

// round 11
// speedup vs baseline: 1.0442x; 1.0001x over previous
#include <cuda_runtime.h>
#include <cstdint>

#define B_   256
#define D_   784
#define H_   1024
#define T_   10
#define NCH  18
#define CHLEN 44

#define KNEG (-1.4426950408889634f)   // -log2(e)

typedef unsigned long long ull;

// ---------------- scratch ----------------
__device__ __align__(16) float g_Wt[D_ * H_];            // (-log2e)*W transposed: [D][H]
__device__ __align__(16) float g_Apre[NCH * B_ * H_];    // scaled chunk-start accumulators
__device__ __align__(16) ull   g_part[D_ * 4 * 4 * 320]; // partial logits [d][tile4][q4][5j][64c]

// ---------------- helpers ----------------
__device__ __forceinline__ float ex2f(float x) {
    float y; asm("ex2.approx.f32 %0, %1;" : "=f"(y) : "f"(x)); return y;
}
__device__ __forceinline__ float rcpf(float x) {
    float y; asm("rcp.approx.f32 %0, %1;" : "=f"(y) : "f"(x)); return y;
}
__device__ __forceinline__ ull fma2_(ull a, ull b, ull c) {
    ull d; asm("fma.rn.f32x2 %0, %1, %2, %3;" : "=l"(d) : "l"(a), "l"(b), "l"(c)); return d;
}
__device__ __forceinline__ ull add2_(ull a, ull b) {
    ull d; asm("add.rn.f32x2 %0, %1, %2;" : "=l"(d) : "l"(a), "l"(b)); return d;
}
__device__ __forceinline__ ull pack2_(float lo, float hi) {
    ull d; asm("mov.b64 %0, {%1, %2};" : "=l"(d) : "f"(lo), "f"(hi)); return d;
}
__device__ __forceinline__ void unpack2_(ull v, float& lo, float& hi) {
    asm("mov.b64 {%0, %1}, %2;" : "=f"(lo), "=f"(hi) : "l"(v));
}
__device__ __forceinline__ void cp_async16(float* s, const float* g) {
    unsigned sa = (unsigned)__cvta_generic_to_shared(s);
    asm volatile("cp.async.ca.shared.global [%0], [%1], 16;\n" :: "r"(sa), "l"(g));
}
__device__ __forceinline__ void cp_commit() {
    asm volatile("cp.async.commit_group;\n" ::: "memory");
}

// ---------------- K1: transpose W [H][D] -> (-log2e)*Wt [D][H] ----------------
__global__ void k_transW(const float* __restrict__ W) {
    __shared__ float tile[32][33];
    int d = blockIdx.x * 32 + threadIdx.x;
    int h = blockIdx.y * 32 + threadIdx.y;
#pragma unroll
    for (int j = 0; j < 32; j += 8)
        if (d < D_) tile[threadIdx.y + j][threadIdx.x] = W[(h + j) * D_ + d] * KNEG;
    __syncthreads();
    int ho = blockIdx.y * 32 + threadIdx.x;
    int do_ = blockIdx.x * 32 + threadIdx.y;
#pragma unroll
    for (int j = 0; j < 32; j += 8)
        if (do_ + j < D_) g_Wt[(do_ + j) * H_ + ho] = tile[threadIdx.x][threadIdx.y + j];
}

// ---------------- K2: chunk sums ----------------
__global__ __launch_bounds__(512) void k_chunksum(const int* __restrict__ x) {
    int bg = blockIdx.x;        // 0..31 (8 batches each)
    int k  = blockIdx.y;
    int i0 = k * CHLEN;
    int len = min(CHLEN, D_ - i0);
    __shared__ float xs2[CHLEN * 8];
    int tid = threadIdx.x;
    for (int idx = tid; idx < len * 8; idx += 512) {
        int j = idx >> 3, b = idx & 7;
        xs2[idx] = (float)x[(size_t)(bg * 8 + b) * D_ + i0 + j];
    }
    __syncthreads();
    int h0 = blockIdx.z * 512 + tid;
    float acc[8];
#pragma unroll
    for (int b = 0; b < 8; b++) acc[b] = 0.f;
    float wn1 = g_Wt[i0 * H_ + h0];
    float wn2 = (len > 1) ? g_Wt[(i0 + 1) * H_ + h0] : 0.f;
    for (int j = 0; j < len; j++) {
        float wv = wn1;
        wn1 = wn2;
        if (j + 2 < len) wn2 = g_Wt[(i0 + j + 2) * H_ + h0];
        const float* xr = &xs2[j * 8];
#pragma unroll
        for (int b = 0; b < 8; b++)
            acc[b] = fmaf(xr[b], wv, acc[b]);
    }
#pragma unroll
    for (int b = 0; b < 8; b++)
        g_Apre[(size_t)(k * B_ + bg * 8 + b) * H_ + h0] = acc[b];
}

// ---------------- K3: exclusive prefix, MLP=18 ----------------
__global__ void k_prefix(const float* __restrict__ c) {
    int idx = blockIdx.x * 256 + threadIdx.x;
    int b  = idx >> 9;
    int h0 = (idx & 511) * 2;
    float2 v[NCH];
#pragma unroll
    for (int k = 0; k < NCH; k++)
        v[k] = *(const float2*)&g_Apre[(size_t)(k * B_ + b) * H_ + h0];
    float2 acc = *(const float2*)&c[h0];
    acc.x *= KNEG; acc.y *= KNEG;
#pragma unroll
    for (int k = 0; k < NCH; k++) {
        *(float2*)&g_Apre[(size_t)(k * B_ + b) * H_ + h0] = acc;
        acc.x += v[k].x; acc.y += v[k].y;
    }
}

// ---------------- K4: main kernel (64 batches x 256 h per block) ----------------
// smem (floats):
#define SM_V   0                        // 3 * 2560 = 7680
#define SM_W   7680                     // 3 * 256  =  768
#define SM_RED 8448                     // 2 * 5120 = 10240 (as ull pairs)
#define SM_FLOATS 18688                 // 74752 B; x2 blocks = 149504 B

__device__ __forceinline__ void stage(float* sm, int i, int srel, int hbase, int tid,
                                      const float* __restrict__ V) {
    const int bb = srel % 3;
    const float* vg = V + (size_t)i * (T_ * H_) + (size_t)hbase * T_;   // 2560 floats
    float* vs = sm + SM_V + bb * 2560;
    cp_async16(vs + tid * 4, vg + tid * 4);
    if (tid < 128) cp_async16(vs + (tid + 512) * 4, vg + (tid + 512) * 4);
    else if (tid < 192)
        cp_async16(sm + SM_W + bb * 256 + (tid - 128) * 4,
                   g_Wt + (size_t)i * H_ + hbase + (tid - 128) * 4);
    cp_async16(vs + (tid + 256) * 4, vg + (tid + 256) * 4);
}

__device__ __forceinline__ void step_compute(float* sm, ull* a2, ull x2,
                                             int hl, int w, int L, int srel) {
    const float* Vp = sm + SM_V + (srel % 3) * 2560;
    const float* Wp = sm + SM_W + (srel % 3) * 256;

    ull accA[5], accB[5];
#pragma unroll
    for (int j = 0; j < 5; j++) { accA[j] = 0ull; accB[j] = 0ull; }

    float sb0, sb1;
    {
        float f0, f1;
        unpack2_(a2[0], f0, f1);
        sb0 = rcpf(1.f + ex2f(f0));
        sb1 = rcpf(1.f + ex2f(f1));
    }

#pragma unroll
    for (int u = 0; u < 32; u++) {      // h = hbase + hl + u; a2[u] = (a_b0, a_b1)
        float nb0 = 0.f, nb1 = 0.f;
        if (u < 31) {
            float f0, f1;
            unpack2_(a2[u + 1], f0, f1);
            nb0 = rcpf(1.f + ex2f(f0));
            nb1 = rcpf(1.f + ex2f(f1));
        }
        const float wv = Wp[hl + u];
        a2[u] = fma2_(x2, pack2_(wv, wv), a2[u]);

        const float* vr = Vp + (hl + u) * T_;     // 40B rows, 8B aligned
        const ull s0 = pack2_(sb0, sb0);
        const ull s1 = pack2_(sb1, sb1);
#pragma unroll
        for (int j = 0; j < 5; j++) {
            const ull vv = *(const ull*)(vr + 2 * j);
            accA[j] = fma2_(s0, vv, accA[j]);
            accB[j] = fma2_(s1, vv, accB[j]);
        }
        sb0 = nb0; sb1 = nb1;
    }

    float* red = sm + SM_RED + (srel & 1) * 5120;
#pragma unroll
    for (int j = 0; j < 5; j++) {
        *(ull*)(red + ((w * 5 + j) * 64 + L) * 2)      = accA[j];
        *(ull*)(red + ((w * 5 + j) * 64 + 32 + L) * 2) = accB[j];
    }
}

__device__ __forceinline__ void reduce_store(const float* sm, ull* gp, int sdone, int L) {
    const float* red = sm + SM_RED + (sdone & 1) * 5120;
#pragma unroll
    for (int j = 0; j < 5; j++)
#pragma unroll
        for (int p = 0; p < 2; p++) {
            const int col = p * 32 + L;
            ull s = *(const ull*)(red + ((0 * 5 + j) * 64 + col) * 2);
#pragma unroll
            for (int ww = 1; ww < 8; ww++)
                s = add2_(s, *(const ull*)(red + ((ww * 5 + j) * 64 + col) * 2));
            gp[j * 64 + col] = s;
        }
}

__global__ __launch_bounds__(256, 2) void k_main(const int* __restrict__ xi,
                                                 const float* __restrict__ V) {
    extern __shared__ float sm[];
    const int tid   = threadIdx.x;
    const int w     = tid >> 5;       // 0..7
    const int L     = tid & 31;
    const int tile  = blockIdx.x;     // 0..3  (64 batches)
    const int chunk = blockIdx.y;     // 0..NCH-1
    const int qh    = blockIdx.z;     // 0..3  (256 h)
    const int i0  = chunk * CHLEN;
    const int len = min(CHLEN, D_ - i0);
    const int hbase = qh * 256;
    const int hl  = w * 32;           // local h within quarter
    const int h0  = hbase + hl;

    // a2[u] = (A[b0][h0+u], A[b1][h0+u]); b0 = tile*64+L, b1 = b0+32
    ull a2[32];
    {
        const float* ap0 = g_Apre + ((size_t)(chunk * B_ + tile * 64 + L)) * H_ + h0;
        const float* ap1 = ap0 + (size_t)32 * H_;
#pragma unroll
        for (int g = 0; g < 8; g++) {
            float4 va = *(const float4*)(ap0 + 4 * g);
            float4 vb = *(const float4*)(ap1 + 4 * g);
            a2[4 * g + 0] = pack2_(va.x, vb.x);
            a2[4 * g + 1] = pack2_(va.y, vb.y);
            a2[4 * g + 2] = pack2_(va.z, vb.z);
            a2[4 * g + 3] = pack2_(va.w, vb.w);
        }
    }

    stage(sm, i0, 0, hbase, tid, V); cp_commit();
    if (len > 1) { stage(sm, i0 + 1, 1, hbase, tid, V); cp_commit(); }

    const int* xrow0 = xi + (size_t)(tile * 64 + L) * D_ + i0;
    const int* xrow1 = xrow0 + (size_t)32 * D_;
    float x0buf[2], x1buf[2];
    x0buf[0] = (float)__ldg(xrow0);     x1buf[0] = (float)__ldg(xrow1);
    x0buf[1] = (len > 1) ? (float)__ldg(xrow0 + 1) : 0.f;
    x1buf[1] = (len > 1) ? (float)__ldg(xrow1 + 1) : 0.f;

    for (int s = 0; s < len; s++) {
        if (s + 1 < len) asm volatile("cp.async.wait_group 1;\n" ::: "memory");
        else             asm volatile("cp.async.wait_group 0;\n" ::: "memory");
        __syncthreads();

        const ull x2 = pack2_(x0buf[s & 1], x1buf[s & 1]);
        if (s + 2 < len) {
            x0buf[s & 1] = (float)__ldg(xrow0 + s + 2);
            x1buf[s & 1] = (float)__ldg(xrow1 + s + 2);
            stage(sm, i0 + s + 2, s + 2, hbase, tid, V); cp_commit();
        }

        if (s >= 1 && w == ((s - 1) & 7)) {
            ull* gp = g_part + ((size_t)((i0 + s - 1) * 4 + tile) * 4 + qh) * 320;
            reduce_store(sm, gp, s - 1, L);
        }

        step_compute(sm, a2, x2, hl, w, L, s);
    }

    __syncthreads();
    if (w == ((len - 1) & 7)) {
        ull* gp = g_part + ((size_t)((i0 + len - 1) * 4 + tile) * 4 + qh) * 320;
        reduce_store(sm, gp, len - 1, L);
    }
}

// ---------------- K5: combine quarters + bias + softmax ----------------
__global__ __launch_bounds__(320) void k_softmax(const float* __restrict__ bias,
                                                 float* __restrict__ out) {
    __shared__ float lg[T_ * 66];
    const int d    = blockIdx.x;      // 0..783
    const int tile = blockIdx.y;      // 0..3
    const int tid  = threadIdx.x;     // 0..319: (j, c)
    const int j = tid >> 6;
    const int c = tid & 63;
    const ull* gp = g_part + ((size_t)(d * 4 + tile) * 4) * 320;
    ull v = gp[tid];
    v = add2_(v, gp[320 + tid]);
    v = add2_(v, gp[640 + tid]);
    v = add2_(v, gp[960 + tid]);
    float lo, hi;
    unpack2_(v, lo, hi);
    lg[(2 * j)     * 66 + c] = lo + bias[d * T_ + 2 * j];
    lg[(2 * j + 1) * 66 + c] = hi + bias[d * T_ + 2 * j + 1];
    __syncthreads();
    if (tid < 64) {
        float l[T_];
#pragma unroll
        for (int t = 0; t < T_; t++) l[t] = lg[t * 66 + tid];
        float mx = l[0];
#pragma unroll
        for (int t = 1; t < T_; t++) mx = fmaxf(mx, l[t]);
        float e[T_]; float sum = 0.f;
#pragma unroll
        for (int t = 0; t < T_; t++) {
            e[t] = ex2f((l[t] - mx) * 1.4426950408889634f);
            sum += e[t];
        }
        const float r = rcpf(sum);
        float* op = out + (size_t)(tile * 64 + tid) * (T_ * D_) + d;
#pragma unroll
        for (int t = 0; t < T_; t++) op[t * D_] = e[t] * r;
    }
}

// ---------------- launch ----------------
extern "C" void kernel_launch(void* const* d_in, const int* in_sizes, int n_in,
                              void* d_out, int out_size) {
    const int*   x    = (const int*)d_in[0];
    const float* W    = (const float*)d_in[1];
    const float* c    = (const float*)d_in[2];
    const float* V    = (const float*)d_in[3];
    const float* bias = (const float*)d_in[4];
    float* out = (float*)d_out;

    static_assert(2 * SM_FLOATS * 4 <= 232448, "smem budget for 2 blocks/SM");
    cudaFuncSetAttribute(k_main, cudaFuncAttributeMaxDynamicSharedMemorySize,
                         SM_FLOATS * (int)sizeof(float));

    k_transW<<<dim3((D_ + 31) / 32, H_ / 32), dim3(32, 8)>>>(W);     // launch 1
    k_chunksum<<<dim3(32, NCH, 2), 512>>>(x);                        // launch 2
    k_prefix<<<(B_ * H_ / 2) / 256, 256>>>(c);                       // launch 3
    k_main<<<dim3(4, NCH, 4), 256, SM_FLOATS * (int)sizeof(float)>>>(x, V);  // launch 4 -> profiled
    k_softmax<<<dim3(D_, 4), 320>>>(bias, out);                      // launch 5
}